// round 14
// baseline (speedup 1.0000x reference)
#include <cuda_runtime.h>

#define B_    32
#define SPAST 4095
#define SEQ   4096
#define H_    2048
#define NH_   16
#define HD_   128
#define QKV_KSPLIT 16
#define PROJ_KSPLIT 32
#define R1_GROUPS 8   // stage-1 reduce groups (PROJ_KSPLIT / 4 partials each)

// Scratch (no allocations allowed) -----------------------------------------
__device__ float g_qkv_part[QKV_KSPLIT * B_ * 3 * H_];  // QKV k-split partials
__device__ float g_ctx[B_ * H_];                        // attention output [32][2048]
__device__ float g_out_part[PROJ_KSPLIT * B_ * H_];     // proj k-split partials
__device__ float g_out_part2[R1_GROUPS * B_ * H_];      // stage-1 reduced partials

// ---------------------------------------------------------------------------
// Skinny GEMM (R6-proven inner loop, 4-warp blocks for residency):
//   P[ks][b][n] = sum_{k in segment ks} X[b][k] * W[k][n]
// Block: 128 threads = 4 warps; warp w covers cols [w*128,(w+1)*128),
// lane owns 4 consecutive cols (one float4 W load, zero redundancy).
// Thread accumulates 16 batch rows (z picks rows 0-15 / 16-31): 64 accs,
// ~150 regs -> 3 blocks (12 warps)/SM. Intensity: 16 FMA per W-float.
// Grid: (N/512, ksplit, 2)
// ---------------------------------------------------------------------------
__global__ __launch_bounds__(128) void gemm_skinny(
    const float* __restrict__ X, const float* __restrict__ W,
    float* __restrict__ P, int N, int kseg) {
  const int t = threadIdx.x;
  const int lane = t & 31;
  const int w = t >> 5;
  const int n0 = blockIdx.x * 512 + w * 128 + lane * 4;
  const int kbeg = blockIdx.y * kseg;
  const int brow0 = blockIdx.z * 16;

  __shared__ float xs[16][36];  // [b][kk]; 36%4==0 keeps float4 quads aligned

  float acc[16][4];
#pragma unroll
  for (int b = 0; b < 16; b++)
#pragma unroll
    for (int c = 0; c < 4; c++) acc[b][c] = 0.f;

  for (int kc = 0; kc < kseg; kc += 32) {
    __syncthreads();
    // stage X chunk: 16 rows x 32 k = 512 floats, coalesced
#pragma unroll
    for (int r = t; r < 512; r += 128) {
      int bb = r >> 5, kk = r & 31;
      xs[bb][kk] = X[(brow0 + bb) * 2048 + kbeg + kc + kk];
    }
    __syncthreads();
#pragma unroll
    for (int kk = 0; kk < 32; kk += 4) {
      const float* wp = W + (size_t)(kbeg + kc + kk) * N + n0;
      float4 w0 = *reinterpret_cast<const float4*>(wp);
      float4 w1 = *reinterpret_cast<const float4*>(wp + N);
      float4 w2 = *reinterpret_cast<const float4*>(wp + 2 * N);
      float4 w3 = *reinterpret_cast<const float4*>(wp + 3 * N);
#pragma unroll
      for (int b = 0; b < 16; b++) {
        float4 x4 = *reinterpret_cast<const float4*>(&xs[b][kk]);
        acc[b][0] += x4.x * w0.x; acc[b][1] += x4.x * w0.y;
        acc[b][2] += x4.x * w0.z; acc[b][3] += x4.x * w0.w;
        acc[b][0] += x4.y * w1.x; acc[b][1] += x4.y * w1.y;
        acc[b][2] += x4.y * w1.z; acc[b][3] += x4.y * w1.w;
        acc[b][0] += x4.z * w2.x; acc[b][1] += x4.z * w2.y;
        acc[b][2] += x4.z * w2.z; acc[b][3] += x4.z * w2.w;
        acc[b][0] += x4.w * w3.x; acc[b][1] += x4.w * w3.y;
        acc[b][2] += x4.w * w3.z; acc[b][3] += x4.w * w3.w;
      }
    }
  }
  float* p = P + (size_t)blockIdx.y * 32 * N;
#pragma unroll
  for (int b = 0; b < 16; b++) {
    float4 v = make_float4(acc[b][0], acc[b][1], acc[b][2], acc[b][3]);
    *reinterpret_cast<float4*>(p + (size_t)(brow0 + b) * N + n0) = v;
  }
}

// Stage 1: part2[g][i] = sum_{k=4g}^{4g+3} P[k][i]   (grid.y = g, full-chip)
__global__ void reduce_stage1(const float4* __restrict__ P,
                              float4* __restrict__ part2, int N4) {
  int i = blockIdx.x * 256 + threadIdx.x;
  int total4 = B_ * N4;
  if (i >= total4) return;
  int g = blockIdx.y;
  const float4* p = P + (size_t)(4 * g) * total4 + i;
  float4 a = p[0];
  float4 v1 = p[(size_t)total4];
  float4 v2 = p[(size_t)2 * total4];
  float4 v3 = p[(size_t)3 * total4];
  a.x += v1.x; a.y += v1.y; a.z += v1.z; a.w += v1.w;
  a.x += v2.x; a.y += v2.y; a.z += v2.z; a.w += v2.w;
  a.x += v3.x; a.y += v3.y; a.z += v3.z; a.w += v3.w;
  part2[(size_t)g * total4 + i] = a;
}

// Stage 2: out[i] = bias[i%N4] + sum_g part2[g][i]
__global__ void reduce_stage2(const float4* __restrict__ part2,
                              const float4* __restrict__ bias,
                              float4* __restrict__ out, int N4) {
  int i = blockIdx.x * 256 + threadIdx.x;
  int total4 = B_ * N4;
  if (i >= total4) return;
  float4 s = bias[i % N4];
#pragma unroll
  for (int g = 0; g < R1_GROUPS; g++) {
    float4 v = part2[(size_t)g * total4 + i];
    s.x += v.x; s.y += v.y; s.z += v.z; s.w += v.w;
  }
  out[i] = s;
}

// ---------------------------------------------------------------------------
// Decode attention: one block per (b, h). 256 threads = 8 warps.
// Fuses the QKV k-split reduction + bias for its own q/k_new/v_new vectors.
// 8-deep row unroll in both passes -> 8 independent LDG.128 in flight/warp.
// ---------------------------------------------------------------------------
__global__ __launch_bounds__(256) void attn_kernel(
    const float* __restrict__ past_key, const float* __restrict__ past_value,
    const float* __restrict__ b_attn) {
  const int h = blockIdx.x;
  const int b = blockIdx.y;
  const int t = threadIdx.x;
  const int lane = t & 31;
  const int wid = t >> 5;

  __shared__ float q_s[HD_], k_s[HD_], v_s[HD_];
  __shared__ float sc[SEQ];       // 16 KB scores
  __shared__ float red[32];
  __shared__ float ctxp[8][HD_];  // 4 KB partial ctx

  // Fused QKV reduction: sum 16 partials + bias for this block's vectors
  if (t < HD_) {
    float qa = b_attn[h * HD_ + t];
    float ka = b_attn[H_ + h * HD_ + t];
    float va = b_attn[2 * H_ + h * HD_ + t];
#pragma unroll
    for (int ks = 0; ks < QKV_KSPLIT; ks++) {
      const float* pp = g_qkv_part + ((size_t)ks * B_ + b) * (3 * H_);
      qa += pp[h * HD_ + t];
      ka += pp[H_ + h * HD_ + t];
      va += pp[2 * H_ + h * HD_ + t];
    }
    q_s[t] = qa * 0.08838834764831845f;  // 1/sqrt(128)
    k_s[t] = ka;
    v_s[t] = va;
  }
  __syncthreads();

  const float4 qv = *reinterpret_cast<const float4*>(&q_s[lane * 4]);
  const float* kbase = past_key + ((size_t)b * SPAST) * H_ + h * HD_;

  // ---- scores: warp handles rows wid*8+j, stride 64; MLP=8 ----
  for (int s0 = wid * 8; s0 < SEQ; s0 += 64) {
    float4 kv[8];
#pragma unroll
    for (int j = 0; j < 8; j++) {
      int s = s0 + j;  // uniform across the warp
      if (s < SPAST)
        kv[j] = __ldg(reinterpret_cast<const float4*>(kbase + (size_t)s * H_) + lane);
      else
        kv[j] = *reinterpret_cast<const float4*>(&k_s[lane * 4]);
    }
#pragma unroll
    for (int j = 0; j < 8; j++) {
      float d = qv.x * kv[j].x + qv.y * kv[j].y + qv.z * kv[j].z + qv.w * kv[j].w;
      d += __shfl_xor_sync(0xffffffffu, d, 16);
      d += __shfl_xor_sync(0xffffffffu, d, 8);
      d += __shfl_xor_sync(0xffffffffu, d, 4);
      d += __shfl_xor_sync(0xffffffffu, d, 2);
      d += __shfl_xor_sync(0xffffffffu, d, 1);
      if (lane == 0) sc[s0 + j] = d;
    }
  }
  __syncthreads();

  // ---- softmax over sc[0..4095] ----
  float m = -3.0e38f;
  for (int i = t; i < SEQ; i += 256) m = fmaxf(m, sc[i]);
#pragma unroll
  for (int o = 16; o; o >>= 1) m = fmaxf(m, __shfl_xor_sync(0xffffffffu, m, o));
  if (lane == 0) red[wid] = m;
  __syncthreads();
  if (t == 0) {
    float mm = red[0];
    for (int ww = 1; ww < 8; ww++) mm = fmaxf(mm, red[ww]);
    red[8] = mm;
  }
  __syncthreads();
  const float gmax = red[8];

  float ls = 0.f;
  for (int i = t; i < SEQ; i += 256) {
    float e = __expf(sc[i] - gmax);
    sc[i] = e;
    ls += e;
  }
#pragma unroll
  for (int o = 16; o; o >>= 1) ls += __shfl_xor_sync(0xffffffffu, ls, o);
  if (lane == 0) red[16 + wid] = ls;
  __syncthreads();
  if (t == 0) {
    float ss = 0.f;
    for (int ww = 0; ww < 8; ww++) ss += red[16 + ww];
    red[24] = 1.0f / ss;
  }
  __syncthreads();
  const float inv = red[24];

  // ---- ctx = probs @ V, rows wid + 8*i, unroll 8 -> MLP=8 ----
  const float* vbase = past_value + ((size_t)b * SPAST) * H_ + h * HD_;
  float4 acc = make_float4(0.f, 0.f, 0.f, 0.f);
  for (int i = 0; i < SEQ / 8; i += 8) {
    float4 vv[8];
    float p[8];
#pragma unroll
    for (int j = 0; j < 8; j++) {
      int s = wid + (i + j) * 8;  // uniform across the warp
      if (s < SPAST)
        vv[j] = __ldg(reinterpret_cast<const float4*>(vbase + (size_t)s * H_) + lane);
      else
        vv[j] = *reinterpret_cast<const float4*>(&v_s[lane * 4]);
      p[j] = sc[s];
    }
#pragma unroll
    for (int j = 0; j < 8; j++) {
      acc.x += p[j] * vv[j].x;
      acc.y += p[j] * vv[j].y;
      acc.z += p[j] * vv[j].z;
      acc.w += p[j] * vv[j].w;
    }
  }
  *reinterpret_cast<float4*>(&ctxp[wid][lane * 4]) = acc;
  __syncthreads();
  if (t < HD_) {
    float v = 0.f;
#pragma unroll
    for (int ww = 0; ww < 8; ww++) v += ctxp[ww][t];
    g_ctx[b * H_ + h * HD_ + t] = v * inv;
  }
}

// ---------------------------------------------------------------------------
extern "C" void kernel_launch(void* const* d_in, const int* in_sizes, int n_in,
                              void* d_out, int out_size) {
  const float* x  = (const float*)d_in[0];   // [32,1,2048]
  const float* pk = (const float*)d_in[1];   // [32,4095,2048]
  const float* pv = (const float*)d_in[2];   // [32,4095,2048]
  const float* Wa = (const float*)d_in[3];   // [2048,6144]
  const float* ba = (const float*)d_in[4];   // [6144]
  const float* Wp = (const float*)d_in[5];   // [2048,2048]
  const float* bp = (const float*)d_in[6];   // [2048]
  float* out = (float*)d_out;                // [32,1,2048] fp32

  float *qkv_part, *ctx, *out_part, *out_part2;
  cudaGetSymbolAddress((void**)&qkv_part, g_qkv_part);
  cudaGetSymbolAddress((void**)&ctx, g_ctx);
  cudaGetSymbolAddress((void**)&out_part, g_out_part);
  cudaGetSymbolAddress((void**)&out_part2, g_out_part2);

  // QKV: N=6144 -> 12 n-blocks (512 cols), K split 16, batch split 2 -> 384 blocks
  gemm_skinny<<<dim3(12, QKV_KSPLIT, 2), 128>>>(x, Wa, qkv_part, 3 * H_, 2048 / QKV_KSPLIT);

  // Attention (fuses QKV reduce+bias): 512 blocks, single wave
  attn_kernel<<<dim3(NH_, B_), 256>>>(pk, pv, ba);

  // Proj: N=2048 -> 4 n-blocks, K split 32 (kseg=64), batch split 2 -> 256 blocks
  gemm_skinny<<<dim3(4, 32, 2), 128>>>(ctx, Wp, out_part, H_, 2048 / PROJ_KSPLIT);

  // Two-stage deterministic k-split reduction + bias
  const int N4 = H_ / 4;                       // 512 float4 per batch row
  reduce_stage1<<<dim3(64, R1_GROUPS), 256>>>(
      (const float4*)out_part, (float4*)out_part2, N4);
  reduce_stage2<<<64, 256>>>(
      (const float4*)out_part2, (const float4*)bp, (float4*)out, N4);
}

// round 15
// speedup vs baseline: 1.0092x; 1.0092x over previous
#include <cuda_runtime.h>

#define B_    32
#define SPAST 4095
#define SEQ   4096
#define H_    2048
#define NH_   16
#define HD_   128
#define QKV_KSPLIT 16
#define PROJ_KSPLIT 32

// Scratch (no allocations allowed) -----------------------------------------
__device__ float g_qkv_part[QKV_KSPLIT * B_ * 3 * H_];  // QKV k-split partials
__device__ float g_ctx[B_ * H_];                        // attention output [32][2048]
__device__ float g_out_part[PROJ_KSPLIT * B_ * H_];     // proj k-split partials

// ---------------------------------------------------------------------------
// Skinny GEMM (R6-proven inner loop, 4-warp blocks for residency):
//   P[ks][b][n] = sum_{k in segment ks} X[b][k] * W[k][n]
// Block: 128 threads = 4 warps; warp w covers cols [w*128,(w+1)*128),
// lane owns 4 consecutive cols (one float4 W load, zero redundancy).
// Thread accumulates 16 batch rows (z picks rows 0-15 / 16-31): 64 accs,
// ~150 regs -> 3 blocks (12 warps)/SM. Intensity: 16 FMA per W-float.
// Grid: (N/512, ksplit, 2)
// ---------------------------------------------------------------------------
__global__ __launch_bounds__(128) void gemm_skinny(
    const float* __restrict__ X, const float* __restrict__ W,
    float* __restrict__ P, int N, int kseg) {
  const int t = threadIdx.x;
  const int lane = t & 31;
  const int w = t >> 5;
  const int n0 = blockIdx.x * 512 + w * 128 + lane * 4;
  const int kbeg = blockIdx.y * kseg;
  const int brow0 = blockIdx.z * 16;

  __shared__ float xs[16][36];  // [b][kk]; 36%4==0 keeps float4 quads aligned

  float acc[16][4];
#pragma unroll
  for (int b = 0; b < 16; b++)
#pragma unroll
    for (int c = 0; c < 4; c++) acc[b][c] = 0.f;

  for (int kc = 0; kc < kseg; kc += 32) {
    __syncthreads();
    // stage X chunk: 16 rows x 32 k = 512 floats, coalesced
#pragma unroll
    for (int r = t; r < 512; r += 128) {
      int bb = r >> 5, kk = r & 31;
      xs[bb][kk] = X[(brow0 + bb) * 2048 + kbeg + kc + kk];
    }
    __syncthreads();
#pragma unroll
    for (int kk = 0; kk < 32; kk += 4) {
      const float* wp = W + (size_t)(kbeg + kc + kk) * N + n0;
      float4 w0 = *reinterpret_cast<const float4*>(wp);
      float4 w1 = *reinterpret_cast<const float4*>(wp + N);
      float4 w2 = *reinterpret_cast<const float4*>(wp + 2 * N);
      float4 w3 = *reinterpret_cast<const float4*>(wp + 3 * N);
#pragma unroll
      for (int b = 0; b < 16; b++) {
        float4 x4 = *reinterpret_cast<const float4*>(&xs[b][kk]);
        acc[b][0] += x4.x * w0.x; acc[b][1] += x4.x * w0.y;
        acc[b][2] += x4.x * w0.z; acc[b][3] += x4.x * w0.w;
        acc[b][0] += x4.y * w1.x; acc[b][1] += x4.y * w1.y;
        acc[b][2] += x4.y * w1.z; acc[b][3] += x4.y * w1.w;
        acc[b][0] += x4.z * w2.x; acc[b][1] += x4.z * w2.y;
        acc[b][2] += x4.z * w2.z; acc[b][3] += x4.z * w2.w;
        acc[b][0] += x4.w * w3.x; acc[b][1] += x4.w * w3.y;
        acc[b][2] += x4.w * w3.z; acc[b][3] += x4.w * w3.w;
      }
    }
  }
  float* p = P + (size_t)blockIdx.y * 32 * N;
#pragma unroll
  for (int b = 0; b < 16; b++) {
    float4 v = make_float4(acc[b][0], acc[b][1], acc[b][2], acc[b][3]);
    *reinterpret_cast<float4*>(p + (size_t)(brow0 + b) * N + n0) = v;
  }
}

// out[b][n] = sum_ks P[ks][b][n] + bias[n]
// Fully unrolled over NSPLIT -> 32 independent LDG.128 in flight per thread.
// Grid: 128 blocks x 128 threads = one thread per output float4.
template <int NSPLIT>
__global__ __launch_bounds__(128) void reduce_bias_kernel(
    const float4* __restrict__ P, const float4* __restrict__ bias,
    float4* __restrict__ out, int N4) {
  int i = blockIdx.x * 128 + threadIdx.x;
  int total4 = B_ * N4;
  if (i >= total4) return;
  float4 v[NSPLIT];
#pragma unroll
  for (int k = 0; k < NSPLIT; k++) v[k] = P[(size_t)k * total4 + i];
  float4 s = bias[i % N4];
#pragma unroll
  for (int k = 0; k < NSPLIT; k++) {
    s.x += v[k].x; s.y += v[k].y; s.z += v[k].z; s.w += v[k].w;
  }
  out[i] = s;
}

// ---------------------------------------------------------------------------
// Decode attention: one block per (b, h). 256 threads = 8 warps.
// Fuses the QKV k-split reduction + bias for its own q/k_new/v_new vectors.
// Max-tracking fused into the score pass (butterfly leaves d in all lanes).
// 8-deep row unroll in both passes -> 8 independent LDG.128 in flight/warp.
// ---------------------------------------------------------------------------
__global__ __launch_bounds__(256) void attn_kernel(
    const float* __restrict__ past_key, const float* __restrict__ past_value,
    const float* __restrict__ b_attn) {
  const int h = blockIdx.x;
  const int b = blockIdx.y;
  const int t = threadIdx.x;
  const int lane = t & 31;
  const int wid = t >> 5;

  __shared__ float q_s[HD_], k_s[HD_], v_s[HD_];
  __shared__ float sc[SEQ];       // 16 KB scores
  __shared__ float red[32];
  __shared__ float ctxp[8][HD_];  // 4 KB partial ctx

  // Fused QKV reduction: sum 16 partials + bias for this block's vectors
  if (t < HD_) {
    float qa = b_attn[h * HD_ + t];
    float ka = b_attn[H_ + h * HD_ + t];
    float va = b_attn[2 * H_ + h * HD_ + t];
#pragma unroll
    for (int ks = 0; ks < QKV_KSPLIT; ks++) {
      const float* pp = g_qkv_part + ((size_t)ks * B_ + b) * (3 * H_);
      qa += pp[h * HD_ + t];
      ka += pp[H_ + h * HD_ + t];
      va += pp[2 * H_ + h * HD_ + t];
    }
    q_s[t] = qa * 0.08838834764831845f;  // 1/sqrt(128)
    k_s[t] = ka;
    v_s[t] = va;
  }
  __syncthreads();

  const float4 qv = *reinterpret_cast<const float4*>(&q_s[lane * 4]);
  const float* kbase = past_key + ((size_t)b * SPAST) * H_ + h * HD_;

  // ---- scores + fused max: warp handles rows wid*8+j, stride 64; MLP=8 ----
  float wmax = -3.0e38f;
  for (int s0 = wid * 8; s0 < SEQ; s0 += 64) {
    float4 kv[8];
#pragma unroll
    for (int j = 0; j < 8; j++) {
      int s = s0 + j;  // uniform across the warp
      if (s < SPAST)
        kv[j] = __ldg(reinterpret_cast<const float4*>(kbase + (size_t)s * H_) + lane);
      else
        kv[j] = *reinterpret_cast<const float4*>(&k_s[lane * 4]);
    }
#pragma unroll
    for (int j = 0; j < 8; j++) {
      float d = qv.x * kv[j].x + qv.y * kv[j].y + qv.z * kv[j].z + qv.w * kv[j].w;
      d += __shfl_xor_sync(0xffffffffu, d, 16);
      d += __shfl_xor_sync(0xffffffffu, d, 8);
      d += __shfl_xor_sync(0xffffffffu, d, 4);
      d += __shfl_xor_sync(0xffffffffu, d, 2);
      d += __shfl_xor_sync(0xffffffffu, d, 1);
      wmax = fmaxf(wmax, d);  // full butterfly -> d identical in all lanes
      if (lane == 0) sc[s0 + j] = d;
    }
  }
  if (lane == 0) red[wid] = wmax;  // warp-uniform
  __syncthreads();

  // ---- softmax (max already known per-warp) ----
  if (t == 0) {
    float mm = red[0];
    for (int ww = 1; ww < 8; ww++) mm = fmaxf(mm, red[ww]);
    red[8] = mm;
  }
  __syncthreads();
  const float gmax = red[8];

  float ls = 0.f;
  for (int i = t; i < SEQ; i += 256) {
    float e = __expf(sc[i] - gmax);
    sc[i] = e;
    ls += e;
  }
#pragma unroll
  for (int o = 16; o; o >>= 1) ls += __shfl_xor_sync(0xffffffffu, ls, o);
  if (lane == 0) red[16 + wid] = ls;
  __syncthreads();
  if (t == 0) {
    float ss = 0.f;
    for (int ww = 0; ww < 8; ww++) ss += red[16 + ww];
    red[24] = 1.0f / ss;
  }
  __syncthreads();
  const float inv = red[24];

  // ---- ctx = probs @ V, rows wid + 8*i, unroll 8 -> MLP=8 ----
  const float* vbase = past_value + ((size_t)b * SPAST) * H_ + h * HD_;
  float4 acc = make_float4(0.f, 0.f, 0.f, 0.f);
  for (int i = 0; i < SEQ / 8; i += 8) {
    float4 vv[8];
    float p[8];
#pragma unroll
    for (int j = 0; j < 8; j++) {
      int s = wid + (i + j) * 8;  // uniform across the warp
      if (s < SPAST)
        vv[j] = __ldg(reinterpret_cast<const float4*>(vbase + (size_t)s * H_) + lane);
      else
        vv[j] = *reinterpret_cast<const float4*>(&v_s[lane * 4]);
      p[j] = sc[s];
    }
#pragma unroll
    for (int j = 0; j < 8; j++) {
      acc.x += p[j] * vv[j].x;
      acc.y += p[j] * vv[j].y;
      acc.z += p[j] * vv[j].z;
      acc.w += p[j] * vv[j].w;
    }
  }
  *reinterpret_cast<float4*>(&ctxp[wid][lane * 4]) = acc;
  __syncthreads();
  if (t < HD_) {
    float v = 0.f;
#pragma unroll
    for (int ww = 0; ww < 8; ww++) v += ctxp[ww][t];
    g_ctx[b * H_ + h * HD_ + t] = v * inv;
  }
}

// ---------------------------------------------------------------------------
extern "C" void kernel_launch(void* const* d_in, const int* in_sizes, int n_in,
                              void* d_out, int out_size) {
  const float* x  = (const float*)d_in[0];   // [32,1,2048]
  const float* pk = (const float*)d_in[1];   // [32,4095,2048]
  const float* pv = (const float*)d_in[2];   // [32,4095,2048]
  const float* Wa = (const float*)d_in[3];   // [2048,6144]
  const float* ba = (const float*)d_in[4];   // [6144]
  const float* Wp = (const float*)d_in[5];   // [2048,2048]
  const float* bp = (const float*)d_in[6];   // [2048]
  float* out = (float*)d_out;                // [32,1,2048] fp32

  float *qkv_part, *ctx, *out_part;
  cudaGetSymbolAddress((void**)&qkv_part, g_qkv_part);
  cudaGetSymbolAddress((void**)&ctx, g_ctx);
  cudaGetSymbolAddress((void**)&out_part, g_out_part);

  // QKV: N=6144 -> 12 n-blocks (512 cols), K split 16, batch split 2 -> 384 blocks
  gemm_skinny<<<dim3(12, QKV_KSPLIT, 2), 128>>>(x, Wa, qkv_part, 3 * H_, 2048 / QKV_KSPLIT);

  // Attention (fuses QKV reduce+bias): 512 blocks, single wave
  attn_kernel<<<dim3(NH_, B_), 256>>>(pk, pv, ba);

  // Proj: N=2048 -> 4 n-blocks, K split 32 (kseg=64), batch split 2 -> 256 blocks
  gemm_skinny<<<dim3(4, PROJ_KSPLIT, 2), 128>>>(ctx, Wp, out_part, H_, 2048 / PROJ_KSPLIT);

  // Unrolled single-stage k-split reduction + bias: 16384 float4 outputs
  reduce_bias_kernel<PROJ_KSPLIT><<<128, 128>>>(
      (const float4*)out_part, (const float4*)bp, (float4*)out, H_ / 4);
}